// round 12
// baseline (speedup 1.0000x reference)
#include <cuda_runtime.h>
#include <math.h>

#define Nn 4096
#define Dd 256
#define Rr 32
#define Kk 3
#define MAXNZ 96
#define ETA 0.5f
#define COEFF 0.03125f          /* r/(n*eps^2) = 32/(4096*0.25) */
#define LN_EPS 1e-5f

// ---------------- device scratch ----------------
__device__ float g_H1[Nn*Dd];
__device__ float g_H2[Nn*Dd];
__device__ float g_ZT[Kk*Nn*Rr];       // [k][n][r]
__device__ float g_M[Kk*Rr*Rr];        // atomically accumulated Z Z^T (pre-COEFF)
__device__ float g_Minv[Kk*Rr*Rr];
__device__ float g_Gcat[Nn*Kk*Rr];     // [n][k*32+r], pre-scaled by ETA*w_k
__device__ float g_agg[Nn*Dd];
__device__ int   g_nnz[Nn];            // true count
__device__ int   g_nnzp[Nn];           // padded to multiple of 8 (pad: col=row, val=0)
__device__ int   g_cols[Nn*MAXNZ];
__device__ float g_vals[Nn*MAXNZ];
__device__ float g_w[Kk];
__device__ float g_lap[Kk];

__device__ __forceinline__ float warp_sum(float v) {
    #pragma unroll
    for (int o = 16; o; o >>= 1) v += __shfl_xor_sync(0xFFFFFFFFu, v, o);
    return v;
}
__device__ __forceinline__ float warp_max(float v) {
    #pragma unroll
    for (int o = 16; o; o >>= 1) v = fmaxf(v, __shfl_xor_sync(0xFFFFFFFFu, v, o));
    return v;
}

// ================= device bodies (256-thread blocks) =================

// ---- CSR row extraction: one warp per row, 8 rows per block ----
__device__ void csr_body(const float* __restrict__ A, int blk) {
    int warp = threadIdx.x >> 5, lane = threadIdx.x & 31;
    int row = blk * 8 + warp;
    const float4* ar = (const float4*)(A + (size_t)row * Nn);
    unsigned mlt = (1u << lane) - 1u;
    int base = 0;
    for (int c0 = 0; c0 < Nn / 4; c0 += 32) {
        float4 v = ar[c0 + lane];
        unsigned b0 = __ballot_sync(0xFFFFFFFFu, v.x != 0.0f);
        unsigned b1 = __ballot_sync(0xFFFFFFFFu, v.y != 0.0f);
        unsigned b2 = __ballot_sync(0xFFFFFFFFu, v.z != 0.0f);
        unsigned b3 = __ballot_sync(0xFFFFFFFFu, v.w != 0.0f);
        int pos = base + __popc(b0 & mlt) + __popc(b1 & mlt)
                       + __popc(b2 & mlt) + __popc(b3 & mlt);
        int cbase = (c0 + lane) * 4;
        if (v.x != 0.0f && pos < MAXNZ) { g_cols[row*MAXNZ+pos] = cbase;     g_vals[row*MAXNZ+pos] = v.x; pos++; }
        if (v.y != 0.0f && pos < MAXNZ) { g_cols[row*MAXNZ+pos] = cbase + 1; g_vals[row*MAXNZ+pos] = v.y; pos++; }
        if (v.z != 0.0f && pos < MAXNZ) { g_cols[row*MAXNZ+pos] = cbase + 2; g_vals[row*MAXNZ+pos] = v.z; pos++; }
        if (v.w != 0.0f && pos < MAXNZ) { g_cols[row*MAXNZ+pos] = cbase + 3; g_vals[row*MAXNZ+pos] = v.w; pos++; }
        base += __popc(b0) + __popc(b1) + __popc(b2) + __popc(b3);
    }
    if (base > MAXNZ) base = MAXNZ;
    int padded = (base + 7) & ~7;
    if (padded > MAXNZ) padded = MAXNZ;
    for (int i = base + lane; i < padded; i += 32) {
        g_cols[row * MAXNZ + i] = row;
        g_vals[row * MAXNZ + i] = 0.0f;
    }
    if (lane == 0) { g_nnz[row] = base; g_nnzp[row] = padded; }
}

// ---- orth pair loss ----
__device__ void orth_body(const float* __restrict__ U, int p, float* dst) {
    const int pk[6] = {0,0,0,1,1,2}, pl[6] = {0,1,2,1,2,2};
    int k = pk[p], l = pl[p];
    int ab = threadIdx.x >> 5, b = threadIdx.x & 31;
    const float* Ua = U + k * Dd * Rr;
    const float* Ub = U + l * Dd * Rr;
    float tot = 0.0f;
    for (int ao = 0; ao < 4; ao++) {
        int a = ao * 8 + ab;
        float g = 0.0f;
        #pragma unroll 8
        for (int d = 0; d < Dd; d++) g += Ua[d * Rr + a] * Ub[d * Rr + b];
        if (k == l && a == b) g -= 1.0f;
        tot += g * g;
    }
    __shared__ float wred_o[8];
    int w = threadIdx.x >> 5, lane = threadIdx.x & 31;
    float s = warp_sum(tot);
    if (lane == 0) wred_o[w] = s;
    __syncthreads();
    if (threadIdx.x == 0) {
        float t = 0.0f;
        #pragma unroll
        for (int q = 0; q < 8; q++) t += wred_o[q];
        atomicAdd(dst, t);
    }
}

// ---- setup scalars ----
__device__ void setup_body(const float* lam, const float* hw, float* tail) {
    if (threadIdx.x == 0) {
        float h0 = hw[0], h1 = hw[1], h2 = hw[2];
        float mx = fmaxf(h0, fmaxf(h1, h2));
        float e0 = expf(h0 - mx), e1 = expf(h1 - mx), e2 = expf(h2 - mx);
        float inv = 1.0f / (e0 + e1 + e2);
        g_w[0] = e0 * inv; g_w[1] = e1 * inv; g_w[2] = e2 * inv;
        for (int k = 0; k < Kk; k++) g_lap[k] = log1pf(expf(lam[k]));
        tail[1] = 0.0f;
        tail[2] = g_w[0]; tail[3] = g_w[1]; tail[4] = g_w[2];
    }
}

// ---- ZM tile: 32 nodes x 32 r over K=256; writes ZT, atomically accumulates M ----
__device__ void zm_body(const float* __restrict__ src, const float* __restrict__ U,
                        int kz, int tile) {
    __shared__ float Hs[32 * 65];    // 32 nodes x 64 d
    __shared__ float Us[64 * 34];    // 64 d x 32 r
    __shared__ float Zs[32 * 36];    // staged Z tile for M pass
    const float* Uk = U + kz * Dd * Rr;
    int t = threadIdx.x;
    int tx = t & 15, ty = t >> 4;    // tx: r-pair, ty: node-pair
    int n0 = tile * 32;
    float a00 = 0.f, a01 = 0.f, a10 = 0.f, a11 = 0.f;
    for (int d0 = 0; d0 < Dd; d0 += 64) {
        const float4* s4 = (const float4*)(src + (size_t)n0 * Dd + d0);
        #pragma unroll
        for (int q = 0; q < 2; q++) {
            int idx = t + q * 256;           // 0..511
            int row = idx >> 4, c4 = idx & 15;
            float4 v = s4[row * 64 + c4];
            float* hp = &Hs[row * 65 + c4 * 4];
            hp[0] = v.x; hp[1] = v.y; hp[2] = v.z; hp[3] = v.w;
        }
        #pragma unroll
        for (int q = 0; q < 2; q++) {
            int idx = t + q * 256;
            int dr = idx >> 3, c4 = idx & 7;
            float4 v = *(const float4*)&Uk[(d0 + dr) * Rr + c4 * 4];
            float* up = &Us[dr * 34 + c4 * 4];
            up[0] = v.x; up[1] = v.y; up[2] = v.z; up[3] = v.w;
        }
        __syncthreads();
        #pragma unroll 8
        for (int d = 0; d < 64; d++) {
            float2 u = *(float2*)&Us[d * 34 + tx * 2];
            float h0 = Hs[(ty * 2) * 65 + d];
            float h1 = Hs[(ty * 2 + 1) * 65 + d];
            a00 += h0 * u.x; a01 += h0 * u.y;
            a10 += h1 * u.x; a11 += h1 * u.y;
        }
        __syncthreads();
    }
    int n_a = ty * 2, n_b = ty * 2 + 1;
    *(float2*)&g_ZT[kz * Nn * Rr + (n0 + n_a) * Rr + tx * 2] = make_float2(a00, a01);
    *(float2*)&g_ZT[kz * Nn * Rr + (n0 + n_b) * Rr + tx * 2] = make_float2(a10, a11);
    Zs[n_a * 36 + tx * 2] = a00; Zs[n_a * 36 + tx * 2 + 1] = a01;
    Zs[n_b * 36 + tx * 2] = a10; Zs[n_b * 36 + tx * 2 + 1] = a11;
    __syncthreads();
    // partial M over this tile: thread owns (i, j0..j0+3)
    int i = t >> 3, j0 = (t & 7) * 4;
    float m0 = 0.f, m1 = 0.f, m2 = 0.f, m3 = 0.f;
    #pragma unroll 8
    for (int n = 0; n < 32; n++) {
        float zi = Zs[n * 36 + i];
        float4 zj = *(float4*)&Zs[n * 36 + j0];
        m0 += zi * zj.x; m1 += zi * zj.y; m2 += zi * zj.z; m3 += zi * zj.w;
    }
    float* Mk = g_M + kz * Rr * Rr + i * Rr + j0;
    atomicAdd(Mk + 0, m0); atomicAdd(Mk + 1, m1);
    atomicAdd(Mk + 2, m2); atomicAdd(Mk + 3, m3);
}

// ---- SpMM: 4 rows per block, branch-free unroll-8 ----
__device__ void spmm_body(const float* __restrict__ src_f, float* __restrict__ dst_f, int blk) {
    int rl = threadIdx.x >> 6, d4 = threadIdx.x & 63;
    int m = blk * 4 + rl;
    __shared__ int   csh[4][MAXNZ];
    __shared__ float vsh[4][MAXNZ];
    int nzp = g_nnzp[m];
    for (int i = d4; i < nzp; i += 64) {
        csh[rl][i] = g_cols[m * MAXNZ + i];
        vsh[rl][i] = g_vals[m * MAXNZ + i];
    }
    __syncthreads();
    const float4* src = (const float4*)src_f;
    float4 acc = make_float4(0.f, 0.f, 0.f, 0.f);
    for (int i = 0; i < nzp; i += 8) {
        float4 x0 = src[csh[rl][i    ] * 64 + d4];
        float4 x1 = src[csh[rl][i + 1] * 64 + d4];
        float4 x2 = src[csh[rl][i + 2] * 64 + d4];
        float4 x3 = src[csh[rl][i + 3] * 64 + d4];
        float4 x4 = src[csh[rl][i + 4] * 64 + d4];
        float4 x5 = src[csh[rl][i + 5] * 64 + d4];
        float4 x6 = src[csh[rl][i + 6] * 64 + d4];
        float4 x7 = src[csh[rl][i + 7] * 64 + d4];
        float v0 = vsh[rl][i],     v1 = vsh[rl][i + 1], v2 = vsh[rl][i + 2], v3 = vsh[rl][i + 3];
        float v4 = vsh[rl][i + 4], v5 = vsh[rl][i + 5], v6 = vsh[rl][i + 6], v7 = vsh[rl][i + 7];
        acc.x += v0*x0.x + v1*x1.x + v2*x2.x + v3*x3.x + v4*x4.x + v5*x5.x + v6*x6.x + v7*x7.x;
        acc.y += v0*x0.y + v1*x1.y + v2*x2.y + v3*x3.y + v4*x4.y + v5*x5.y + v6*x6.y + v7*x7.y;
        acc.z += v0*x0.z + v1*x1.z + v2*x2.z + v3*x3.z + v4*x4.z + v5*x5.z + v6*x6.z + v7*x7.z;
        acc.w += v0*x0.w + v1*x1.w + v2*x2.w + v3*x3.w + v4*x4.w + v5*x5.w + v6*x6.w + v7*x7.w;
    }
    ((float4*)dst_f)[m * 64 + d4] = acc;
}

// ---- Cholesky + inverse from g_M, 256 threads ----
__device__ void cholinv_body(int kz) {
    __shared__ float Msh[Rr * 33];
    __shared__ float ysh[Rr * 33];
    int t = threadIdx.x;
    for (int e = t; e < Rr * Rr; e += 256) {
        int i = e >> 5, j = e & 31;
        Msh[i * 33 + j] = COEFF * g_M[kz * Rr * Rr + e] + (i == j ? 1.0f : 0.0f);
    }
    __syncthreads();
    for (int k2 = 0; k2 < Rr; k2++) {
        if (t == 0) Msh[k2 * 33 + k2] = sqrtf(Msh[k2 * 33 + k2]);
        __syncthreads();
        if (t > k2 && t < Rr) Msh[t * 33 + k2] /= Msh[k2 * 33 + k2];
        __syncthreads();
        for (int e = t; e < Rr * Rr; e += 256) {
            int i = e >> 5, j = e & 31;
            if (i > k2 && j > k2 && j <= i)
                Msh[i * 33 + j] -= Msh[i * 33 + k2] * Msh[j * 33 + k2];
        }
        __syncthreads();
    }
    // solves: warp w handles columns c = w, w+8, w+16, w+24
    int w = t >> 5, lane = t & 31;
    for (int cc = 0; cc < 4; cc++) {
        int c = w + cc * 8;
        for (int r = 0; r < Rr; r++) {
            float contrib = (lane < r) ? Msh[r * 33 + lane] * ysh[c * 33 + lane] : 0.0f;
            contrib = warp_sum(contrib);
            if (lane == 0) ysh[c * 33 + r] = (((r == c) ? 1.0f : 0.0f) - contrib) / Msh[r * 33 + r];
            __syncwarp();
        }
        for (int r = Rr - 1; r >= 0; r--) {
            float contrib = (lane > r) ? Msh[lane * 33 + r] * ysh[c * 33 + lane] : 0.0f;
            contrib = warp_sum(contrib);
            if (lane == 0) ysh[c * 33 + r] = (ysh[c * 33 + r] - contrib) / Msh[r * 33 + r];
            __syncwarp();
        }
    }
    __syncthreads();
    for (int e = t; e < Rr * Rr; e += 256) {
        int i = e >> 5, j = e & 31;
        g_Minv[kz * Rr * Rr + i * Rr + j] = ysh[j * 33 + i];
    }
}

// ---- attention: warp per query row (round-5 proven version) ----
__device__ void attn_body(int kz, int blk) {
    __shared__ float Mi[Rr * 33];
    __shared__ float ssh[8][MAXNZ];
    int tid = threadIdx.x;
    for (int q = tid; q < Rr * Rr; q += 256)
        Mi[(q >> 5) * 33 + (q & 31)] = g_Minv[kz * Rr * Rr + q];
    __syncthreads();
    int w = tid >> 5, lane = tid & 31;
    int m = blk * 8 + w;
    int nz = g_nnz[m];
    const int* cp = &g_cols[m * MAXNZ];
    const float* ZTk = g_ZT + kz * Nn * Rr;
    float z = ZTk[m * Rr + lane];
    float qp = 0.0f;
    #pragma unroll
    for (int r = 0; r < Rr; r++)
        qp += Mi[r * 33 + lane] * __shfl_sync(0xFFFFFFFFu, z, r);
    for (int i0 = 0; i0 < nz; i0 += 4) {
        int c0 = cp[i0];
        int c1 = (i0 + 1 < nz) ? cp[i0 + 1] : c0;
        int c2 = (i0 + 2 < nz) ? cp[i0 + 2] : c0;
        int c3 = (i0 + 3 < nz) ? cp[i0 + 3] : c0;
        float p0 = warp_sum(qp * ZTk[c0 * Rr + lane]);
        float p1 = warp_sum(qp * ZTk[c1 * Rr + lane]);
        float p2 = warp_sum(qp * ZTk[c2 * Rr + lane]);
        float p3 = warp_sum(qp * ZTk[c3 * Rr + lane]);
        if (lane == 0) {
            ssh[w][i0] = p0;
            if (i0 + 1 < nz) ssh[w][i0 + 1] = p1;
            if (i0 + 2 < nz) ssh[w][i0 + 2] = p2;
            if (i0 + 3 < nz) ssh[w][i0 + 3] = p3;
        }
    }
    __syncwarp();
    float mx = -1e30f;
    for (int i = lane; i < nz; i += 32) mx = fmaxf(mx, ssh[w][i]);
    mx = warp_max(mx);
    float sm = 0.0f;
    for (int i = lane; i < nz; i += 32) {
        float e = expf(ssh[w][i] - mx);
        ssh[w][i] = e; sm += e;
    }
    sm = warp_sum(sm);
    float inv = 1.0f / sm;
    __syncwarp();
    float tacc = 0.0f;
    int i = 0;
    for (; i + 4 <= nz; i += 4) {
        float m0 = ZTk[cp[i]     * Rr + lane];
        float m1 = ZTk[cp[i + 1] * Rr + lane];
        float m2 = ZTk[cp[i + 2] * Rr + lane];
        float m3 = ZTk[cp[i + 3] * Rr + lane];
        tacc += ssh[w][i] * m0 + ssh[w][i + 1] * m1 + ssh[w][i + 2] * m2 + ssh[w][i + 3] * m3;
    }
    for (; i < nz; i++) tacc += ssh[w][i] * ZTk[cp[i] * Rr + lane];
    tacc *= inv;
    float o = 0.0f;
    #pragma unroll
    for (int s2 = 0; s2 < Rr; s2++)
        o += Mi[lane * 33 + s2] * __shfl_sync(0xFFFFFFFFu, tacc, s2);
    g_Gcat[m * (Kk * Rr) + kz * Rr + lane] = o * (ETA * g_w[kz]);
}

// ================= kernels =================

// k_pre: CSR (0..511) + orth (512..517) + setup (518) + ZM k0 (519..646)
__global__ void k_pre(const float* __restrict__ A, const float* __restrict__ U,
                      const float* __restrict__ H,
                      const float* __restrict__ lam, const float* __restrict__ hw,
                      float* __restrict__ tail) {
    int b = blockIdx.x;
    if (b < 512)        csr_body(A, b);
    else if (b < 518)   orth_body(U, b - 512, tail + 0);
    else if (b == 518)  setup_body(lam, hw, tail);
    else                zm_body(H, U, 0, b - 519);
}

// k_spmm1: H -> H1
__global__ void k_spmm1(const float* __restrict__ H) {
    spmm_body(H, g_H1, blockIdx.x);
}

// k_mix1: spmm H1->H2 (0..1023) + ZM k1 (1024..1151)
__global__ void k_mix1(const float* __restrict__ U) {
    int b = blockIdx.x;
    if (b < 1024) spmm_body(g_H1, g_H2, b);
    else          zm_body(g_H1, U, 1, b - 1024);
}

// k_mix2: ZM k2 (0..127) + cholinv k0 (128) + cholinv k1 (129)
__global__ void k_mix2(const float* __restrict__ U) {
    int b = blockIdx.x;
    if (b < 128)      zm_body(g_H2, U, 2, b);
    else if (b == 128) cholinv_body(0);
    else               cholinv_body(1);
}

// k_mix3: attn k0 (0..511) + attn k1 (512..1023) + cholinv k2 (1024)
__global__ void k_mix3() {
    int b = blockIdx.x;
    if (b < 1024) attn_body(b >> 9, b & 511);
    else          cholinv_body(2);
}

// k_attn2: attn k2
__global__ void k_attn2() {
    attn_body(2, blockIdx.x);
}

// ---------------- agg = Gcat @ Ucat: tiled 64x64, 4x4 per thread ----------------
__global__ void k_gemm(const float* __restrict__ U) {
    __shared__ float Gs[64][33];
    __shared__ float Us[32][65];
    int n0 = blockIdx.x * 64, d0 = blockIdx.y * 64;
    int tx = threadIdx.x & 15, ty = threadIdx.x >> 4;
    float acc[4][4];
    #pragma unroll
    for (int a = 0; a < 4; a++)
        #pragma unroll
        for (int b = 0; b < 4; b++) acc[a][b] = 0.f;
    for (int k = 0; k < Kk; k++) {
        __syncthreads();
        #pragma unroll
        for (int q = 0; q < 8; q++) {
            int idx = threadIdx.x + 256 * q;
            int gi = idx >> 5, gr = idx & 31;
            Gs[gi][gr] = g_Gcat[(n0 + gi) * (Kk * Rr) + k * Rr + gr];
            Us[gr][gi] = U[k * Dd * Rr + (d0 + gi) * Rr + gr];
        }
        __syncthreads();
        #pragma unroll
        for (int r = 0; r < Rr; r++) {
            float a[4], b[4];
            #pragma unroll
            for (int q = 0; q < 4; q++) a[q] = Gs[ty * 4 + q][r];
            #pragma unroll
            for (int p = 0; p < 4; p++) b[p] = Us[r][tx * 4 + p];
            #pragma unroll
            for (int q = 0; q < 4; q++)
                #pragma unroll
                for (int p = 0; p < 4; p++) acc[q][p] += a[q] * b[p];
        }
    }
    #pragma unroll
    for (int q = 0; q < 4; q++) {
        float4 v = make_float4(acc[q][0], acc[q][1], acc[q][2], acc[q][3]);
        *(float4*)&g_agg[(size_t)(n0 + ty * 4 + q) * Dd + d0 + tx * 4] = v;
    }
}

// ---------------- finalize: inline H3 gather + threshold + residual + LN ----------------
__global__ void k_finalize(const float* __restrict__ H0, const float* __restrict__ thr,
                           const float* __restrict__ gam, const float* __restrict__ bet,
                           float* __restrict__ out) {
    int rl = threadIdx.x >> 6, t64 = threadIdx.x & 63;
    int m = blockIdx.x * 4 + rl;
    __shared__ int   csh[4][MAXNZ];
    __shared__ float vsh[4][MAXNZ];
    __shared__ float wred[8][2];
    int nzp = g_nnzp[m];
    for (int i = t64; i < nzp; i += 64) {
        csh[rl][i] = g_cols[m * MAXNZ + i];
        vsh[rl][i] = g_vals[m * MAXNZ + i];
    }
    __syncthreads();
    const float4* H0_4 = (const float4*)H0;
    const float4* H1_4 = (const float4*)g_H1;
    const float4* H2_4 = (const float4*)g_H2;
    const float4* ag4  = (const float4*)g_agg;
    int idx4 = m * 64 + t64;
    float4 x  = H0_4[idx4];
    float4 h1 = H1_4[idx4];
    float4 h2 = H2_4[idx4];
    float4 ag = ag4[idx4];
    float4 h3 = make_float4(0.f, 0.f, 0.f, 0.f);
    for (int i = 0; i < nzp; i += 4) {
        float4 x0 = H2_4[csh[rl][i]     * 64 + t64];
        float4 x1 = H2_4[csh[rl][i + 1] * 64 + t64];
        float4 x2 = H2_4[csh[rl][i + 2] * 64 + t64];
        float4 x3 = H2_4[csh[rl][i + 3] * 64 + t64];
        float v0 = vsh[rl][i], v1 = vsh[rl][i + 1], v2 = vsh[rl][i + 2], v3 = vsh[rl][i + 3];
        h3.x += v0*x0.x + v1*x1.x + v2*x2.x + v3*x3.x;
        h3.y += v0*x0.y + v1*x1.y + v2*x2.y + v3*x3.y;
        h3.z += v0*x0.z + v1*x1.z + v2*x2.z + v3*x3.z;
        h3.w += v0*x0.w + v1*x1.w + v2*x2.w + v3*x3.w;
    }
    float l0 = g_lap[0], l1 = g_lap[1], l2 = g_lap[2];
    float4 t4 = ((const float4*)thr)[t64];
    float y[4];
    {
        float xs[4] = {x.x, x.y, x.z, x.w};
        float a1[4] = {h1.x, h1.y, h1.z, h1.w};
        float a2[4] = {h2.x, h2.y, h2.z, h2.w};
        float a3[4] = {h3.x, h3.y, h3.z, h3.w};
        float ags[4] = {ag.x, ag.y, ag.z, ag.w};
        float ts[4] = {t4.x, t4.y, t4.z, t4.w};
        #pragma unroll
        for (int q = 0; q < 4; q++) {
            float lap = l0 * (xs[q] - a1[q]) + l1 * (a1[q] - a2[q]) + l2 * (a2[q] - a3[q]);
            float h = xs[q] + ags[q] - ETA * lap;
            float a = fabsf(h) - ts[q];
            float yv = (a > 0.0f) ? copysignf(a, h) : 0.0f;
            y[q] = yv + xs[q];
        }
    }
    float s1 = y[0] + y[1] + y[2] + y[3];
    float s2 = y[0]*y[0] + y[1]*y[1] + y[2]*y[2] + y[3]*y[3];
    s1 = warp_sum(s1); s2 = warp_sum(s2);
    int w = threadIdx.x >> 5, lane = threadIdx.x & 31;
    if (lane == 0) { wred[w][0] = s1; wred[w][1] = s2; }
    __syncthreads();
    float mu  = (wred[rl*2][0] + wred[rl*2+1][0]) * (1.0f / Dd);
    float ex2 = (wred[rl*2][1] + wred[rl*2+1][1]) * (1.0f / Dd);
    float inv_sd = rsqrtf(ex2 - mu * mu + LN_EPS);
    float4 g4 = ((const float4*)gam)[t64];
    float4 b4 = ((const float4*)bet)[t64];
    float4 o4;
    o4.x = (y[0] - mu) * inv_sd * g4.x + b4.x;
    o4.y = (y[1] - mu) * inv_sd * g4.y + b4.y;
    o4.z = (y[2] - mu) * inv_sd * g4.z + b4.z;
    o4.w = (y[3] - mu) * inv_sd * g4.w + b4.w;
    ((float4*)out)[idx4] = o4;
}

// ---------------- lap_smooth = sum(H_out * (H_out - A@H_out)) ----------------
__global__ void k_lapsm(const float* __restrict__ out, float* __restrict__ dst) {
    int rl = threadIdx.x >> 6, t64 = threadIdx.x & 63;
    int m = blockIdx.x * 4 + rl;
    __shared__ int   csh[4][MAXNZ];
    __shared__ float vsh[4][MAXNZ];
    __shared__ float wred[8];
    int nzp = g_nnzp[m];
    for (int i = t64; i < nzp; i += 64) {
        csh[rl][i] = g_cols[m * MAXNZ + i];
        vsh[rl][i] = g_vals[m * MAXNZ + i];
    }
    __syncthreads();
    const float4* o4 = (const float4*)out;
    float4 o = o4[m * 64 + t64];
    float4 ah = make_float4(0.f, 0.f, 0.f, 0.f);
    for (int i = 0; i < nzp; i += 4) {
        float4 x0 = o4[csh[rl][i]     * 64 + t64];
        float4 x1 = o4[csh[rl][i + 1] * 64 + t64];
        float4 x2 = o4[csh[rl][i + 2] * 64 + t64];
        float4 x3 = o4[csh[rl][i + 3] * 64 + t64];
        float v0 = vsh[rl][i], v1 = vsh[rl][i + 1], v2 = vsh[rl][i + 2], v3 = vsh[rl][i + 3];
        ah.x += v0*x0.x + v1*x1.x + v2*x2.x + v3*x3.x;
        ah.y += v0*x0.y + v1*x1.y + v2*x2.y + v3*x3.y;
        ah.z += v0*x0.z + v1*x1.z + v2*x2.z + v3*x3.z;
        ah.w += v0*x0.w + v1*x1.w + v2*x2.w + v3*x3.w;
    }
    float part = o.x * (o.x - ah.x) + o.y * (o.y - ah.y) + o.z * (o.z - ah.z) + o.w * (o.w - ah.w);
    int w = threadIdx.x >> 5, lane = threadIdx.x & 31;
    float s = warp_sum(part);
    if (lane == 0) wred[w] = s;
    __syncthreads();
    if (threadIdx.x == 0) {
        float t = 0.0f;
        #pragma unroll
        for (int q = 0; q < 8; q++) t += wred[q];
        atomicAdd(dst, t);
    }
}

// ---------------- launch ----------------
extern "C" void kernel_launch(void* const* d_in, const int* in_sizes, int n_in,
                              void* d_out, int out_size) {
    const float* H   = (const float*)d_in[0];
    const float* A   = (const float*)d_in[1];
    const float* U   = (const float*)d_in[4];
    const float* lam = (const float*)d_in[5];
    const float* hw  = (const float*)d_in[6];
    const float* thr = (const float*)d_in[7];
    const float* gam = (const float*)d_in[8];
    const float* bet = (const float*)d_in[9];
    float* out  = (float*)d_out;
    float* tail = out + (size_t)Nn * Dd;   // [orth, lap_smooth, w0, w1, w2]

    void* gM_ptr = 0;
    cudaGetSymbolAddress(&gM_ptr, g_M);

    cudaMemsetAsync(tail, 0, 2 * sizeof(float));
    cudaMemsetAsync(gM_ptr, 0, sizeof(float) * Kk * Rr * Rr);

    k_pre<<<647, 256>>>(A, U, H, lam, hw, tail);   // CSR + orth + setup + ZM(k0)
    k_spmm1<<<Nn / 4, 256>>>(H);                   // H1 = A @ H
    k_mix1<<<1152, 256>>>(U);                      // H2 = A @ H1  +  ZM(k1)
    k_mix2<<<130, 256>>>(U);                       // ZM(k2) + cholinv(k0,k1)
    k_mix3<<<1025, 256>>>();                       // attn(k0,k1) + cholinv(k2)
    k_attn2<<<Nn / 8, 256>>>();                    // attn(k2)
    k_gemm<<<dim3(Nn / 64, Dd / 64), 256>>>(U);
    k_finalize<<<Nn / 4, 256>>>(H, thr, gam, bet, out);  // includes H3 gather
    k_lapsm<<<Nn / 4, 256>>>(out, tail + 1);
}

// round 16
// speedup vs baseline: 1.8234x; 1.8234x over previous
#include <cuda_runtime.h>
#include <math.h>

#define Nn 4096
#define Dd 256
#define Rr 32
#define Kk 3
#define MAXNZ 96
#define ETA 0.5f
#define COEFF 0.03125f          /* r/(n*eps^2) = 32/(4096*0.25) */
#define LN_EPS 1e-5f
#define NCHUNK 64               /* ZM tiles per hop (64-node tiles) */

// ---------------- device scratch ----------------
__device__ float g_H1[Nn*Dd];
__device__ float g_H2[Nn*Dd];
__device__ float g_ZT[Kk*Nn*Rr];          // [k][n][r]
__device__ float g_part[Kk*NCHUNK*Rr*Rr]; // [k][chunk][32*32]
__device__ float g_Minv[Kk*Rr*Rr];
__device__ float g_Gcat[Nn*Kk*Rr];        // [n][k*32+r], pre-scaled by ETA*w_k
__device__ float g_agg[Nn*Dd];
__device__ int   g_nnz[Nn];               // true count
__device__ int   g_nnzp[Nn];              // padded to multiple of 8 (pad: col=row, val=0)
__device__ int   g_cols[Nn*MAXNZ];
__device__ float g_vals[Nn*MAXNZ];
__device__ float g_w[Kk];
__device__ float g_lap[Kk];

__device__ __forceinline__ float warp_sum(float v) {
    #pragma unroll
    for (int o = 16; o; o >>= 1) v += __shfl_xor_sync(0xFFFFFFFFu, v, o);
    return v;
}
__device__ __forceinline__ float warp_max(float v) {
    #pragma unroll
    for (int o = 16; o; o >>= 1) v = fmaxf(v, __shfl_xor_sync(0xFFFFFFFFu, v, o));
    return v;
}

// ---------------- setup ----------------
__global__ void k_setup(const float* lam, const float* hw, float* tail) {
    if (threadIdx.x == 0) {
        float h0 = hw[0], h1 = hw[1], h2 = hw[2];
        float mx = fmaxf(h0, fmaxf(h1, h2));
        float e0 = expf(h0 - mx), e1 = expf(h1 - mx), e2 = expf(h2 - mx);
        float inv = 1.0f / (e0 + e1 + e2);
        g_w[0] = e0 * inv; g_w[1] = e1 * inv; g_w[2] = e2 * inv;
        for (int k = 0; k < Kk; k++) g_lap[k] = log1pf(expf(lam[k]));
        tail[0] = 0.0f; tail[1] = 0.0f;
        tail[2] = g_w[0]; tail[3] = g_w[1]; tail[4] = g_w[2];
    }
}

// ---------------- CSR extraction, float4 + lane prefix scan, padded to 8 ----------------
__global__ void k_csr(const float* __restrict__ A) {
    int warp = threadIdx.x >> 5, lane = threadIdx.x & 31;
    int row = blockIdx.x * 8 + warp;
    const float4* ar = (const float4*)(A + (size_t)row * Nn);
    int base = 0;
    for (int c0 = 0; c0 < Nn / 4; c0 += 32) {
        float4 v = ar[c0 + lane];
        int cnt = (v.x != 0.0f) + (v.y != 0.0f) + (v.z != 0.0f) + (v.w != 0.0f);
        int incl = cnt;
        #pragma unroll
        for (int o = 1; o < 32; o <<= 1) {
            int t = __shfl_up_sync(0xFFFFFFFFu, incl, o);
            if (lane >= o) incl += t;
        }
        int pos = base + incl - cnt;
        int cbase = (c0 + lane) * 4;
        if (v.x != 0.0f && pos < MAXNZ) { g_cols[row*MAXNZ+pos] = cbase;     g_vals[row*MAXNZ+pos] = v.x; pos++; }
        if (v.y != 0.0f && pos < MAXNZ) { g_cols[row*MAXNZ+pos] = cbase + 1; g_vals[row*MAXNZ+pos] = v.y; pos++; }
        if (v.z != 0.0f && pos < MAXNZ) { g_cols[row*MAXNZ+pos] = cbase + 2; g_vals[row*MAXNZ+pos] = v.z; pos++; }
        if (v.w != 0.0f && pos < MAXNZ) { g_cols[row*MAXNZ+pos] = cbase + 3; g_vals[row*MAXNZ+pos] = v.w; pos++; }
        base += __shfl_sync(0xFFFFFFFFu, incl, 31);
    }
    if (base > MAXNZ) base = MAXNZ;
    int padded = (base + 7) & ~7;
    if (padded > MAXNZ) padded = MAXNZ;
    for (int i = base + lane; i < padded; i += 32) {
        g_cols[row * MAXNZ + i] = row;
        g_vals[row * MAXNZ + i] = 0.0f;
    }
    if (lane == 0) { g_nnz[row] = base; g_nnzp[row] = padded; }
}

// ---------------- orthogonality loss (1024 threads, 6 blocks) ----------------
__global__ void k_orth(const float* __restrict__ U, float* __restrict__ dst) {
    const int pk[6] = {0,0,0,1,1,2}, pl[6] = {0,1,2,1,2,2};
    int k = pk[blockIdx.x], l = pl[blockIdx.x];
    int a = threadIdx.x >> 5, b = threadIdx.x & 31;
    const float* Ua = U + k * Dd * Rr;
    const float* Ub = U + l * Dd * Rr;
    float g = 0.0f;
    #pragma unroll 8
    for (int d = 0; d < Dd; d++) g += Ua[d * Rr + a] * Ub[d * Rr + b];
    if (k == l && a == b) g -= 1.0f;
    g *= g;
    __shared__ float wred[32];
    int w = threadIdx.x >> 5, lane = threadIdx.x & 31;
    float s = warp_sum(g);
    if (lane == 0) wred[w] = s;
    __syncthreads();
    if (threadIdx.x < 32) {
        float t = wred[threadIdx.x];
        t = warp_sum(t);
        if (threadIdx.x == 0) atomicAdd(dst, t);
    }
}

// ---------------- SpMM float4, 4 rows per block, branch-free unroll-8 ----------------
__global__ void k_spmm(const float* __restrict__ H0, int src_id, int dst_id) {
    int rl = threadIdx.x >> 6, d4 = threadIdx.x & 63;
    int m = blockIdx.x * 4 + rl;
    __shared__ int   csh[4][MAXNZ];
    __shared__ float vsh[4][MAXNZ];
    int nzp = g_nnzp[m];
    for (int i = d4; i < nzp; i += 64) {
        csh[rl][i] = g_cols[m * MAXNZ + i];
        vsh[rl][i] = g_vals[m * MAXNZ + i];
    }
    __syncthreads();
    const float4* src = (const float4*)((src_id == 0) ? H0 : g_H1);
    float4 acc = make_float4(0.f, 0.f, 0.f, 0.f);
    for (int i = 0; i < nzp; i += 8) {
        float4 x0 = src[csh[rl][i    ] * 64 + d4];
        float4 x1 = src[csh[rl][i + 1] * 64 + d4];
        float4 x2 = src[csh[rl][i + 2] * 64 + d4];
        float4 x3 = src[csh[rl][i + 3] * 64 + d4];
        float4 x4 = src[csh[rl][i + 4] * 64 + d4];
        float4 x5 = src[csh[rl][i + 5] * 64 + d4];
        float4 x6 = src[csh[rl][i + 6] * 64 + d4];
        float4 x7 = src[csh[rl][i + 7] * 64 + d4];
        float v0 = vsh[rl][i],     v1 = vsh[rl][i + 1], v2 = vsh[rl][i + 2], v3 = vsh[rl][i + 3];
        float v4 = vsh[rl][i + 4], v5 = vsh[rl][i + 5], v6 = vsh[rl][i + 6], v7 = vsh[rl][i + 7];
        acc.x += v0*x0.x + v1*x1.x + v2*x2.x + v3*x3.x + v4*x4.x + v5*x5.x + v6*x6.x + v7*x7.x;
        acc.y += v0*x0.y + v1*x1.y + v2*x2.y + v3*x3.y + v4*x4.y + v5*x5.y + v6*x6.y + v7*x7.y;
        acc.z += v0*x0.z + v1*x1.z + v2*x2.z + v3*x3.z + v4*x4.z + v5*x5.z + v6*x6.z + v7*x7.z;
        acc.w += v0*x0.w + v1*x1.w + v2*x2.w + v3*x3.w + v4*x4.w + v5*x5.w + v6*x6.w + v7*x7.w;
    }
    float4* dst = (float4*)((dst_id == 1) ? g_H1 : g_H2);
    dst[m * 64 + d4] = acc;
}

// ---------------- fused: ZT tile GEMM + partial M, 64-node tiles (grid 64 x 3) ----------------
__global__ void k_ZM(const float* __restrict__ H0, const float* __restrict__ U) {
    __shared__ float Hs[64 * 33];    // 64 nodes x 32 d-chunk (also reused as Z tile)
    __shared__ float Us[32][32];
    int kz = blockIdx.y;
    const float* src = (kz == 0) ? H0 : (kz == 1) ? g_H1 : g_H2;
    const float* Uk = U + kz * Dd * Rr;
    int n0 = blockIdx.x * 64;
    int tx = threadIdx.x & 15;   // r-pair: r = tx*2, tx*2+1
    int ty = threadIdx.x >> 4;   // node group: rows ty*4 .. ty*4+3
    float acc[4][2];
    #pragma unroll
    for (int q = 0; q < 4; q++) { acc[q][0] = 0.f; acc[q][1] = 0.f; }
    for (int d0 = 0; d0 < Dd; d0 += 32) {
        const float4* s4 = (const float4*)(src + (size_t)n0 * Dd + d0);
        // load 64 rows x 32 floats = 512 float4; 2 per thread
        #pragma unroll
        for (int q = 0; q < 2; q++) {
            int idx = threadIdx.x + q * 256;
            int row = idx >> 3, cc = idx & 7;
            float4 v = s4[row * 64 + cc];
            float* hp = &Hs[row * 33 + cc * 4];
            hp[0] = v.x; hp[1] = v.y; hp[2] = v.z; hp[3] = v.w;
        }
        int kk = threadIdx.x >> 3, c4 = threadIdx.x & 7;
        *(float4*)&Us[kk][c4 * 4] = *(const float4*)&Uk[(d0 + kk) * Rr + c4 * 4];
        __syncthreads();
        #pragma unroll
        for (int k2 = 0; k2 < 32; k2++) {
            float b0 = Us[k2][tx * 2], b1 = Us[k2][tx * 2 + 1];
            #pragma unroll
            for (int q = 0; q < 4; q++) {
                float a = Hs[(ty * 4 + q) * 33 + k2];
                acc[q][0] += a * b0; acc[q][1] += a * b1;
            }
        }
        __syncthreads();
    }
    // write ZT and stash z-tile into Hs (reused as [64][33])
    #pragma unroll
    for (int q = 0; q < 4; q++) {
        int n = ty * 4 + q;
        *(float2*)&g_ZT[kz * Nn * Rr + (n0 + n) * Rr + tx * 2] = make_float2(acc[q][0], acc[q][1]);
        Hs[n * 33 + tx * 2] = acc[q][0];
        Hs[n * 33 + tx * 2 + 1] = acc[q][1];
    }
    __syncthreads();
    // partial M over this 64-node chunk: thread owns 2x2 of the 32x32 output
    int i0 = (threadIdx.x >> 4) * 2, j0 = (threadIdx.x & 15) * 2;
    float a00 = 0.f, a01 = 0.f, a10 = 0.f, a11 = 0.f;
    #pragma unroll 4
    for (int n = 0; n < 64; n++) {
        float zi0 = Hs[n * 33 + i0], zi1 = Hs[n * 33 + i0 + 1];
        float zj0 = Hs[n * 33 + j0], zj1 = Hs[n * 33 + j0 + 1];
        a00 += zi0 * zj0; a01 += zi0 * zj1;
        a10 += zi1 * zj0; a11 += zi1 * zj1;
    }
    float* p = g_part + (kz * NCHUNK + blockIdx.x) * Rr * Rr;
    p[i0 * 32 + j0] = a00; p[i0 * 32 + j0 + 1] = a01;
    p[(i0 + 1) * 32 + j0] = a10; p[(i0 + 1) * 32 + j0 + 1] = a11;
}

// ---------------- reduce + Cholesky + inverse (3 blocks of 1024) ----------------
__global__ void k_cholinv() {
    __shared__ float Msh[Rr * 33];
    __shared__ float ysh[Rr * 33];
    int kz = blockIdx.x;
    int tid = threadIdx.x;
    int i = tid >> 5, j = tid & 31;
    float s = 0.0f;
    #pragma unroll
    for (int b = 0; b < NCHUNK; b++) s += g_part[(kz * NCHUNK + b) * Rr * Rr + tid];
    Msh[i * 33 + j] = COEFF * s + (i == j ? 1.0f : 0.0f);
    __syncthreads();
    for (int k2 = 0; k2 < Rr; k2++) {
        if (tid == 0) Msh[k2 * 33 + k2] = sqrtf(Msh[k2 * 33 + k2]);
        __syncthreads();
        if (j == k2 && i > k2) Msh[i * 33 + k2] /= Msh[k2 * 33 + k2];
        __syncthreads();
        if (i > k2 && j > k2 && j <= i) Msh[i * 33 + j] -= Msh[i * 33 + k2] * Msh[j * 33 + k2];
        __syncthreads();
    }
    int c = i, lane = j;
    for (int r = 0; r < Rr; r++) {
        float contrib = (lane < r) ? Msh[r * 33 + lane] * ysh[c * 33 + lane] : 0.0f;
        contrib = warp_sum(contrib);
        if (lane == 0) ysh[c * 33 + r] = (((r == c) ? 1.0f : 0.0f) - contrib) / Msh[r * 33 + r];
        __syncwarp();
    }
    for (int r = Rr - 1; r >= 0; r--) {
        float contrib = (lane > r) ? Msh[lane * 33 + r] * ysh[c * 33 + lane] : 0.0f;
        contrib = warp_sum(contrib);
        if (lane == 0) ysh[c * 33 + r] = (ysh[c * 33 + r] - contrib) / Msh[r * 33 + r];
        __syncwarp();
    }
    __syncthreads();
    g_Minv[kz * Rr * Rr + i * 32 + j] = ysh[j * 33 + i];   // Minv[i][c=j]
}

// ---------------- attention: applies Minv in-kernel, warp per row ----------------
__global__ void k_attn() {
    __shared__ float Mi[Rr * 33];
    __shared__ float ssh[8][MAXNZ];
    int kz = blockIdx.y;
    int tid = threadIdx.x;
    for (int q = tid; q < Rr * Rr; q += 256)
        Mi[(q >> 5) * 33 + (q & 31)] = g_Minv[kz * Rr * Rr + q];
    __syncthreads();
    int w = tid >> 5, lane = tid & 31;
    int m = blockIdx.x * 8 + w;
    int nz = g_nnz[m];
    const int* cp = &g_cols[m * MAXNZ];
    const float* ZTk = g_ZT + kz * Nn * Rr;
    float z = ZTk[m * Rr + lane];
    // qp[s] = sum_r z[r] * Minv[r][s]
    float qp = 0.0f;
    #pragma unroll
    for (int r = 0; r < Rr; r++)
        qp += Mi[r * 33 + lane] * __shfl_sync(0xFFFFFFFFu, z, r);
    // scores over neighbors
    for (int i0 = 0; i0 < nz; i0 += 4) {
        int c0 = cp[i0];
        int c1 = (i0 + 1 < nz) ? cp[i0 + 1] : c0;
        int c2 = (i0 + 2 < nz) ? cp[i0 + 2] : c0;
        int c3 = (i0 + 3 < nz) ? cp[i0 + 3] : c0;
        float p0 = warp_sum(qp * ZTk[c0 * Rr + lane]);
        float p1 = warp_sum(qp * ZTk[c1 * Rr + lane]);
        float p2 = warp_sum(qp * ZTk[c2 * Rr + lane]);
        float p3 = warp_sum(qp * ZTk[c3 * Rr + lane]);
        if (lane == 0) {
            ssh[w][i0] = p0;
            if (i0 + 1 < nz) ssh[w][i0 + 1] = p1;
            if (i0 + 2 < nz) ssh[w][i0 + 2] = p2;
            if (i0 + 3 < nz) ssh[w][i0 + 3] = p3;
        }
    }
    __syncwarp();
    float mx = -1e30f;
    for (int i = lane; i < nz; i += 32) mx = fmaxf(mx, ssh[w][i]);
    mx = warp_max(mx);
    float sm = 0.0f;
    for (int i = lane; i < nz; i += 32) {
        float e = expf(ssh[w][i] - mx);
        ssh[w][i] = e; sm += e;
    }
    sm = warp_sum(sm);
    float inv = 1.0f / sm;
    __syncwarp();
    // t = sum_j alpha_j * z_j
    float t = 0.0f;
    int i = 0;
    for (; i + 4 <= nz; i += 4) {
        float m0 = ZTk[cp[i]     * Rr + lane];
        float m1 = ZTk[cp[i + 1] * Rr + lane];
        float m2 = ZTk[cp[i + 2] * Rr + lane];
        float m3 = ZTk[cp[i + 3] * Rr + lane];
        t += ssh[w][i] * m0 + ssh[w][i + 1] * m1 + ssh[w][i + 2] * m2 + ssh[w][i + 3] * m3;
    }
    for (; i < nz; i++) t += ssh[w][i] * ZTk[cp[i] * Rr + lane];
    t *= inv;
    // out[r] = sum_s Minv[r][s] * t[s]
    float o = 0.0f;
    #pragma unroll
    for (int s2 = 0; s2 < Rr; s2++)
        o += Mi[lane * 33 + s2] * __shfl_sync(0xFFFFFFFFu, t, s2);
    g_Gcat[m * (Kk * Rr) + kz * Rr + lane] = o * (ETA * g_w[kz]);
}

// ---------------- agg = Gcat @ Ucat: tiled 64x64, 4x4 per thread ----------------
__global__ void k_gemm(const float* __restrict__ U) {
    __shared__ float Gs[64][33];
    __shared__ float Us[32][65];
    int n0 = blockIdx.x * 64, d0 = blockIdx.y * 64;
    int tx = threadIdx.x & 15, ty = threadIdx.x >> 4;
    float acc[4][4];
    #pragma unroll
    for (int a = 0; a < 4; a++)
        #pragma unroll
        for (int b = 0; b < 4; b++) acc[a][b] = 0.f;
    for (int k = 0; k < Kk; k++) {
        __syncthreads();
        #pragma unroll
        for (int q = 0; q < 8; q++) {
            int idx = threadIdx.x + 256 * q;
            int gi = idx >> 5, gr = idx & 31;
            Gs[gi][gr] = g_Gcat[(n0 + gi) * (Kk * Rr) + k * Rr + gr];
            Us[gr][gi] = U[k * Dd * Rr + (d0 + gi) * Rr + gr];
        }
        __syncthreads();
        #pragma unroll
        for (int r = 0; r < Rr; r++) {
            float a[4], b[4];
            #pragma unroll
            for (int q = 0; q < 4; q++) a[q] = Gs[ty * 4 + q][r];
            #pragma unroll
            for (int p = 0; p < 4; p++) b[p] = Us[r][tx * 4 + p];
            #pragma unroll
            for (int q = 0; q < 4; q++)
                #pragma unroll
                for (int p = 0; p < 4; p++) acc[q][p] += a[q] * b[p];
        }
    }
    #pragma unroll
    for (int q = 0; q < 4; q++) {
        float4 v = make_float4(acc[q][0], acc[q][1], acc[q][2], acc[q][3]);
        *(float4*)&g_agg[(size_t)(n0 + ty * 4 + q) * Dd + d0 + tx * 4] = v;
    }
}

// ---------------- finalize: inline H3 gather + threshold + residual + LN; 4 rows/block ----------------
__global__ void k_finalize(const float* __restrict__ H0, const float* __restrict__ thr,
                           const float* __restrict__ gam, const float* __restrict__ bet,
                           float* __restrict__ out) {
    int rl = threadIdx.x >> 6, t64 = threadIdx.x & 63;
    int m = blockIdx.x * 4 + rl;
    __shared__ int   csh[4][MAXNZ];
    __shared__ float vsh[4][MAXNZ];
    __shared__ float wred[8][2];
    int nzp = g_nnzp[m];
    for (int i = t64; i < nzp; i += 64) {
        csh[rl][i] = g_cols[m * MAXNZ + i];
        vsh[rl][i] = g_vals[m * MAXNZ + i];
    }
    __syncthreads();
    const float4* H0_4 = (const float4*)H0;
    const float4* H1_4 = (const float4*)g_H1;
    const float4* H2_4 = (const float4*)g_H2;
    const float4* ag4  = (const float4*)g_agg;
    int idx4 = m * 64 + t64;
    float4 x  = H0_4[idx4];
    float4 h1 = H1_4[idx4];
    float4 h2 = H2_4[idx4];
    float4 ag = ag4[idx4];
    float4 h3 = make_float4(0.f, 0.f, 0.f, 0.f);
    for (int i = 0; i < nzp; i += 4) {
        float4 x0 = H2_4[csh[rl][i]     * 64 + t64];
        float4 x1 = H2_4[csh[rl][i + 1] * 64 + t64];
        float4 x2 = H2_4[csh[rl][i + 2] * 64 + t64];
        float4 x3 = H2_4[csh[rl][i + 3] * 64 + t64];
        float v0 = vsh[rl][i], v1 = vsh[rl][i + 1], v2 = vsh[rl][i + 2], v3 = vsh[rl][i + 3];
        h3.x += v0*x0.x + v1*x1.x + v2*x2.x + v3*x3.x;
        h3.y += v0*x0.y + v1*x1.y + v2*x2.y + v3*x3.y;
        h3.z += v0*x0.z + v1*x1.z + v2*x2.z + v3*x3.z;
        h3.w += v0*x0.w + v1*x1.w + v2*x2.w + v3*x3.w;
    }
    float l0 = g_lap[0], l1 = g_lap[1], l2 = g_lap[2];
    float4 t4 = ((const float4*)thr)[t64];
    float y[4];
    {
        float xs[4] = {x.x, x.y, x.z, x.w};
        float a1[4] = {h1.x, h1.y, h1.z, h1.w};
        float a2[4] = {h2.x, h2.y, h2.z, h2.w};
        float a3[4] = {h3.x, h3.y, h3.z, h3.w};
        float ags[4] = {ag.x, ag.y, ag.z, ag.w};
        float ts[4] = {t4.x, t4.y, t4.z, t4.w};
        #pragma unroll
        for (int q = 0; q < 4; q++) {
            float lap = l0 * (xs[q] - a1[q]) + l1 * (a1[q] - a2[q]) + l2 * (a2[q] - a3[q]);
            float h = xs[q] + ags[q] - ETA * lap;
            float a = fabsf(h) - ts[q];
            float yv = (a > 0.0f) ? copysignf(a, h) : 0.0f;
            y[q] = yv + xs[q];
        }
    }
    float s1 = y[0] + y[1] + y[2] + y[3];
    float s2 = y[0]*y[0] + y[1]*y[1] + y[2]*y[2] + y[3]*y[3];
    s1 = warp_sum(s1); s2 = warp_sum(s2);
    int w = threadIdx.x >> 5, lane = threadIdx.x & 31;
    if (lane == 0) { wred[w][0] = s1; wred[w][1] = s2; }
    __syncthreads();
    float mu  = (wred[rl*2][0] + wred[rl*2+1][0]) * (1.0f / Dd);
    float ex2 = (wred[rl*2][1] + wred[rl*2+1][1]) * (1.0f / Dd);
    float inv_sd = rsqrtf(ex2 - mu * mu + LN_EPS);
    float4 g4 = ((const float4*)gam)[t64];
    float4 b4 = ((const float4*)bet)[t64];
    float4 o4;
    o4.x = (y[0] - mu) * inv_sd * g4.x + b4.x;
    o4.y = (y[1] - mu) * inv_sd * g4.y + b4.y;
    o4.z = (y[2] - mu) * inv_sd * g4.z + b4.z;
    o4.w = (y[3] - mu) * inv_sd * g4.w + b4.w;
    ((float4*)out)[idx4] = o4;
}

// ---------------- lap_smooth = sum(H_out * (H_out - A@H_out)); 4 rows/block ----------------
__global__ void k_lapsm(const float* __restrict__ out, float* __restrict__ dst) {
    int rl = threadIdx.x >> 6, t64 = threadIdx.x & 63;
    int m = blockIdx.x * 4 + rl;
    __shared__ int   csh[4][MAXNZ];
    __shared__ float vsh[4][MAXNZ];
    __shared__ float wred[8];
    int nzp = g_nnzp[m];
    for (int i = t64; i < nzp; i += 64) {
        csh[rl][i] = g_cols[m * MAXNZ + i];
        vsh[rl][i] = g_vals[m * MAXNZ + i];
    }
    __syncthreads();
    const float4* o4 = (const float4*)out;
    float4 o = o4[m * 64 + t64];
    float4 ah = make_float4(0.f, 0.f, 0.f, 0.f);
    for (int i = 0; i < nzp; i += 4) {
        float4 x0 = o4[csh[rl][i]     * 64 + t64];
        float4 x1 = o4[csh[rl][i + 1] * 64 + t64];
        float4 x2 = o4[csh[rl][i + 2] * 64 + t64];
        float4 x3 = o4[csh[rl][i + 3] * 64 + t64];
        float v0 = vsh[rl][i], v1 = vsh[rl][i + 1], v2 = vsh[rl][i + 2], v3 = vsh[rl][i + 3];
        ah.x += v0*x0.x + v1*x1.x + v2*x2.x + v3*x3.x;
        ah.y += v0*x0.y + v1*x1.y + v2*x2.y + v3*x3.y;
        ah.z += v0*x0.z + v1*x1.z + v2*x2.z + v3*x3.z;
        ah.w += v0*x0.w + v1*x1.w + v2*x2.w + v3*x3.w;
    }
    float part = o.x * (o.x - ah.x) + o.y * (o.y - ah.y) + o.z * (o.z - ah.z) + o.w * (o.w - ah.w);
    int w = threadIdx.x >> 5, lane = threadIdx.x & 31;
    float s = warp_sum(part);
    if (lane == 0) wred[w] = s;
    __syncthreads();
    if (threadIdx.x == 0) {
        float t = 0.0f;
        #pragma unroll
        for (int q = 0; q < 8; q++) t += wred[q];
        atomicAdd(dst, t);
    }
}

// ---------------- launch ----------------
extern "C" void kernel_launch(void* const* d_in, const int* in_sizes, int n_in,
                              void* d_out, int out_size) {
    const float* H   = (const float*)d_in[0];
    const float* A   = (const float*)d_in[1];
    const float* U   = (const float*)d_in[4];
    const float* lam = (const float*)d_in[5];
    const float* hw  = (const float*)d_in[6];
    const float* thr = (const float*)d_in[7];
    const float* gam = (const float*)d_in[8];
    const float* bet = (const float*)d_in[9];
    float* out  = (float*)d_out;
    float* tail = out + (size_t)Nn * Dd;   // [orth, lap_smooth, w0, w1, w2]

    k_setup<<<1, 32>>>(lam, hw, tail);
    k_csr<<<Nn / 8, 256>>>(A);
    k_orth<<<6, 1024>>>(U, tail + 0);

    k_spmm<<<Nn / 4, 256>>>(H, 0, 1);   // H1 = A @ H
    k_spmm<<<Nn / 4, 256>>>(H, 1, 2);   // H2 = A @ H1

    k_ZM<<<dim3(NCHUNK, Kk), 256>>>(H, U);  // ZT + partial M, 64-node tiles
    k_cholinv<<<Kk, 1024>>>();
    k_attn<<<dim3(Nn / 8, Kk), 256>>>();

    k_gemm<<<dim3(Nn / 64, Dd / 64), 256>>>(U);
    k_finalize<<<Nn / 4, 256>>>(H, thr, gam, bet, out);  // includes H3 gather
    k_lapsm<<<Nn / 4, 256>>>(out, tail + 1);
}

// round 17
// speedup vs baseline: 2.1125x; 1.1585x over previous
#include <cuda_runtime.h>
#include <math.h>

#define Nn 4096
#define Dd 256
#define Rr 32
#define Kk 3
#define MAXNZ 96
#define ETA 0.5f
#define COEFF 0.03125f          /* r/(n*eps^2) = 32/(4096*0.25) */
#define LN_EPS 1e-5f
#define HSTR 36                 /* ZM Hs row stride (float4-aligned padding) */

// ---------------- device scratch ----------------
__device__ float g_H1[Nn*Dd];
__device__ float g_H2[Nn*Dd];
__device__ float g_ZT[Kk*Nn*Rr];       // [k][n][r]
__device__ float g_part[Kk*32*Rr*Rr];  // [k][chunk][32*32]
__device__ float g_Minv[Kk*Rr*Rr];
__device__ float g_Gcat[Nn*Kk*Rr];     // [n][k*32+r], pre-scaled by ETA*w_k
__device__ float g_agg[Nn*Dd];
__device__ int   g_nnz[Nn];            // true count
__device__ int   g_nnzp[Nn];           // padded to multiple of 8 (pad: col=row, val=0)
__device__ int   g_cols[Nn*MAXNZ];
__device__ float g_vals[Nn*MAXNZ];
__device__ float g_w[Kk];
__device__ float g_lap[Kk];

__device__ __forceinline__ float warp_sum(float v) {
    #pragma unroll
    for (int o = 16; o; o >>= 1) v += __shfl_xor_sync(0xFFFFFFFFu, v, o);
    return v;
}
__device__ __forceinline__ float warp_max(float v) {
    #pragma unroll
    for (int o = 16; o; o >>= 1) v = fmaxf(v, __shfl_xor_sync(0xFFFFFFFFu, v, o));
    return v;
}

// ---------------- CSR extraction, float4 + lane prefix scan, padded to 8 ----------------
__global__ void k_csr(const float* __restrict__ A) {
    int warp = threadIdx.x >> 5, lane = threadIdx.x & 31;
    int row = blockIdx.x * 8 + warp;
    const float4* ar = (const float4*)(A + (size_t)row * Nn);
    int base = 0;
    for (int c0 = 0; c0 < Nn / 4; c0 += 32) {
        float4 v = ar[c0 + lane];
        int cnt = (v.x != 0.0f) + (v.y != 0.0f) + (v.z != 0.0f) + (v.w != 0.0f);
        int incl = cnt;
        #pragma unroll
        for (int o = 1; o < 32; o <<= 1) {
            int t = __shfl_up_sync(0xFFFFFFFFu, incl, o);
            if (lane >= o) incl += t;
        }
        int pos = base + incl - cnt;
        int cbase = (c0 + lane) * 4;
        if (v.x != 0.0f && pos < MAXNZ) { g_cols[row*MAXNZ+pos] = cbase;     g_vals[row*MAXNZ+pos] = v.x; pos++; }
        if (v.y != 0.0f && pos < MAXNZ) { g_cols[row*MAXNZ+pos] = cbase + 1; g_vals[row*MAXNZ+pos] = v.y; pos++; }
        if (v.z != 0.0f && pos < MAXNZ) { g_cols[row*MAXNZ+pos] = cbase + 2; g_vals[row*MAXNZ+pos] = v.z; pos++; }
        if (v.w != 0.0f && pos < MAXNZ) { g_cols[row*MAXNZ+pos] = cbase + 3; g_vals[row*MAXNZ+pos] = v.w; pos++; }
        base += __shfl_sync(0xFFFFFFFFu, incl, 31);
    }
    if (base > MAXNZ) base = MAXNZ;
    int padded = (base + 7) & ~7;
    if (padded > MAXNZ) padded = MAXNZ;
    for (int i = base + lane; i < padded; i += 32) {
        g_cols[row * MAXNZ + i] = row;
        g_vals[row * MAXNZ + i] = 0.0f;
    }
    if (lane == 0) { g_nnz[row] = base; g_nnzp[row] = padded; }
}

// ---------------- SpMM float4, 4 rows per block, branch-free unroll-8 ----------------
__global__ void k_spmm(const float* __restrict__ H0, int src_id, int dst_id) {
    int rl = threadIdx.x >> 6, d4 = threadIdx.x & 63;
    int m = blockIdx.x * 4 + rl;
    __shared__ int   csh[4][MAXNZ];
    __shared__ float vsh[4][MAXNZ];
    int nzp = g_nnzp[m];
    for (int i = d4; i < nzp; i += 64) {
        csh[rl][i] = g_cols[m * MAXNZ + i];
        vsh[rl][i] = g_vals[m * MAXNZ + i];
    }
    __syncthreads();
    const float4* src = (const float4*)((src_id == 0) ? H0 : g_H1);
    float4 acc = make_float4(0.f, 0.f, 0.f, 0.f);
    for (int i = 0; i < nzp; i += 8) {
        float4 x0 = src[csh[rl][i    ] * 64 + d4];
        float4 x1 = src[csh[rl][i + 1] * 64 + d4];
        float4 x2 = src[csh[rl][i + 2] * 64 + d4];
        float4 x3 = src[csh[rl][i + 3] * 64 + d4];
        float4 x4 = src[csh[rl][i + 4] * 64 + d4];
        float4 x5 = src[csh[rl][i + 5] * 64 + d4];
        float4 x6 = src[csh[rl][i + 6] * 64 + d4];
        float4 x7 = src[csh[rl][i + 7] * 64 + d4];
        float v0 = vsh[rl][i],     v1 = vsh[rl][i + 1], v2 = vsh[rl][i + 2], v3 = vsh[rl][i + 3];
        float v4 = vsh[rl][i + 4], v5 = vsh[rl][i + 5], v6 = vsh[rl][i + 6], v7 = vsh[rl][i + 7];
        acc.x += v0*x0.x + v1*x1.x + v2*x2.x + v3*x3.x + v4*x4.x + v5*x5.x + v6*x6.x + v7*x7.x;
        acc.y += v0*x0.y + v1*x1.y + v2*x2.y + v3*x3.y + v4*x4.y + v5*x5.y + v6*x6.y + v7*x7.y;
        acc.z += v0*x0.z + v1*x1.z + v2*x2.z + v3*x3.z + v4*x4.z + v5*x5.z + v6*x6.z + v7*x7.z;
        acc.w += v0*x0.w + v1*x1.w + v2*x2.w + v3*x3.w + v4*x4.w + v5*x5.w + v6*x6.w + v7*x7.w;
    }
    float4* dst = (float4*)((dst_id == 1) ? g_H1 : g_H2);
    dst[m * 64 + d4] = acc;
}

// ---------------- fused: ZT tile GEMM + partial M (grid 32 x 3), vectorized LDS ----------------
__global__ void k_ZM(const float* __restrict__ H0, const float* __restrict__ U) {
    __shared__ float Hs[128 * HSTR];   // 128 nodes x 32 d-chunk, stride 36 (16B aligned rows)
    __shared__ float Us[32][32];
    int kz = blockIdx.y;
    const float* src = (kz == 0) ? H0 : (kz == 1) ? g_H1 : g_H2;
    const float* Uk = U + kz * Dd * Rr;
    int n0 = blockIdx.x * 128;
    int tx = threadIdx.x & 15;   // r-pair: r = tx*2, tx*2+1
    int ty = threadIdx.x >> 4;   // node group: rows ty*8 .. ty*8+7
    float acc[8][2];
    #pragma unroll
    for (int q = 0; q < 8; q++) { acc[q][0] = 0.f; acc[q][1] = 0.f; }
    for (int d0 = 0; d0 < Dd; d0 += 32) {
        const float4* s4 = (const float4*)(src + (size_t)n0 * Dd + d0);
        int rr = threadIdx.x >> 3, cc = threadIdx.x & 7;
        #pragma unroll
        for (int q = 0; q < 4; q++) {
            float4 v = s4[(rr + q * 32) * 64 + cc];
            *(float4*)&Hs[(rr + q * 32) * HSTR + cc * 4] = v;
        }
        int kk = threadIdx.x >> 3, c4 = threadIdx.x & 7;
        *(float4*)&Us[kk][c4 * 4] = *(const float4*)&Uk[(d0 + kk) * Rr + c4 * 4];
        __syncthreads();
        #pragma unroll
        for (int k2 = 0; k2 < 32; k2 += 4) {
            float2 u0 = *(float2*)&Us[k2    ][tx * 2];
            float2 u1 = *(float2*)&Us[k2 + 1][tx * 2];
            float2 u2 = *(float2*)&Us[k2 + 2][tx * 2];
            float2 u3 = *(float2*)&Us[k2 + 3][tx * 2];
            #pragma unroll
            for (int q = 0; q < 8; q++) {
                float4 h = *(float4*)&Hs[(ty * 8 + q) * HSTR + k2];
                acc[q][0] += h.x * u0.x + h.y * u1.x + h.z * u2.x + h.w * u3.x;
                acc[q][1] += h.x * u0.y + h.y * u1.y + h.z * u2.y + h.w * u3.y;
            }
        }
        __syncthreads();
    }
    // write ZT and stash z-tile in smem (reuse Hs as [128][HSTR])
    #pragma unroll
    for (int q = 0; q < 8; q++) {
        int n = ty * 8 + q;
        *(float2*)&g_ZT[kz * Nn * Rr + (n0 + n) * Rr + tx * 2] = make_float2(acc[q][0], acc[q][1]);
        Hs[n * HSTR + tx * 2] = acc[q][0];
        Hs[n * HSTR + tx * 2 + 1] = acc[q][1];
    }
    __syncthreads();
    // partial M over this 128-node chunk: thread owns 2x2 of the 32x32 output
    int i0 = (threadIdx.x >> 4) * 2, j0 = (threadIdx.x & 15) * 2;
    float a00 = 0.f, a01 = 0.f, a10 = 0.f, a11 = 0.f;
    #pragma unroll 4
    for (int n = 0; n < 128; n++) {
        float zi0 = Hs[n * HSTR + i0], zi1 = Hs[n * HSTR + i0 + 1];
        float zj0 = Hs[n * HSTR + j0], zj1 = Hs[n * HSTR + j0 + 1];
        a00 += zi0 * zj0; a01 += zi0 * zj1;
        a10 += zi1 * zj0; a11 += zi1 * zj1;
    }
    float* p = g_part + (kz * 32 + blockIdx.x) * Rr * Rr;
    p[i0 * 32 + j0] = a00; p[i0 * 32 + j0 + 1] = a01;
    p[(i0 + 1) * 32 + j0] = a10; p[(i0 + 1) * 32 + j0 + 1] = a11;
}

// ---------------- merged mid kernel (grid 10 x 1024) ----------------
// blocks 0..2: reduce + Cholesky + inverse (per hop)
// blocks 3..8: orth pair loss
// block  9   : setup scalars
__global__ void k_mid(const float* __restrict__ U, const float* __restrict__ lam,
                      const float* __restrict__ hw, float* __restrict__ tail) {
    int blk = blockIdx.x;
    if (blk < 3) {
        __shared__ float Msh[Rr * 33];
        __shared__ float ysh[Rr * 33];
        int kz = blk;
        int tid = threadIdx.x;
        int i = tid >> 5, j = tid & 31;
        float s = 0.0f;
        #pragma unroll
        for (int b = 0; b < 32; b++) s += g_part[(kz * 32 + b) * Rr * Rr + tid];
        Msh[i * 33 + j] = COEFF * s + (i == j ? 1.0f : 0.0f);
        __syncthreads();
        for (int k2 = 0; k2 < Rr; k2++) {
            if (tid == 0) Msh[k2 * 33 + k2] = sqrtf(Msh[k2 * 33 + k2]);
            __syncthreads();
            if (j == k2 && i > k2) Msh[i * 33 + k2] /= Msh[k2 * 33 + k2];
            __syncthreads();
            if (i > k2 && j > k2 && j <= i) Msh[i * 33 + j] -= Msh[i * 33 + k2] * Msh[j * 33 + k2];
            __syncthreads();
        }
        int c = i, lane = j;
        for (int r = 0; r < Rr; r++) {
            float contrib = (lane < r) ? Msh[r * 33 + lane] * ysh[c * 33 + lane] : 0.0f;
            contrib = warp_sum(contrib);
            if (lane == 0) ysh[c * 33 + r] = (((r == c) ? 1.0f : 0.0f) - contrib) / Msh[r * 33 + r];
            __syncwarp();
        }
        for (int r = Rr - 1; r >= 0; r--) {
            float contrib = (lane > r) ? Msh[lane * 33 + r] * ysh[c * 33 + lane] : 0.0f;
            contrib = warp_sum(contrib);
            if (lane == 0) ysh[c * 33 + r] = (ysh[c * 33 + r] - contrib) / Msh[r * 33 + r];
            __syncwarp();
        }
        __syncthreads();
        g_Minv[kz * Rr * Rr + i * 32 + j] = ysh[j * 33 + i];   // Minv[i][c=j]
    } else if (blk < 9) {
        const int pk[6] = {0,0,0,1,1,2}, pl[6] = {0,1,2,1,2,2};
        int p = blk - 3;
        int k = pk[p], l = pl[p];
        int a = threadIdx.x >> 5, b = threadIdx.x & 31;
        const float* Ua = U + k * Dd * Rr;
        const float* Ub = U + l * Dd * Rr;
        float g = 0.0f;
        #pragma unroll 8
        for (int d = 0; d < Dd; d++) g += Ua[d * Rr + a] * Ub[d * Rr + b];
        if (k == l && a == b) g -= 1.0f;
        g *= g;
        __shared__ float wred[32];
        int w = threadIdx.x >> 5, lane = threadIdx.x & 31;
        float s = warp_sum(g);
        if (lane == 0) wred[w] = s;
        __syncthreads();
        if (threadIdx.x < 32) {
            float t = wred[threadIdx.x];
            t = warp_sum(t);
            if (threadIdx.x == 0) atomicAdd(tail + 0, t);
        }
    } else {
        if (threadIdx.x == 0) {
            float h0 = hw[0], h1 = hw[1], h2 = hw[2];
            float mx = fmaxf(h0, fmaxf(h1, h2));
            float e0 = expf(h0 - mx), e1 = expf(h1 - mx), e2 = expf(h2 - mx);
            float inv = 1.0f / (e0 + e1 + e2);
            g_w[0] = e0 * inv; g_w[1] = e1 * inv; g_w[2] = e2 * inv;
            for (int k = 0; k < Kk; k++) g_lap[k] = log1pf(expf(lam[k]));
            tail[2] = g_w[0]; tail[3] = g_w[1]; tail[4] = g_w[2];
        }
    }
}

// ---------------- attention: applies Minv in-kernel, warp per row ----------------
__global__ void k_attn() {
    __shared__ float Mi[Rr * 33];
    __shared__ float ssh[8][MAXNZ];
    int kz = blockIdx.y;
    int tid = threadIdx.x;
    for (int q = tid; q < Rr * Rr; q += 256)
        Mi[(q >> 5) * 33 + (q & 31)] = g_Minv[kz * Rr * Rr + q];
    __syncthreads();
    int w = tid >> 5, lane = tid & 31;
    int m = blockIdx.x * 8 + w;
    int nz = g_nnz[m];
    const int* cp = &g_cols[m * MAXNZ];
    const float* ZTk = g_ZT + kz * Nn * Rr;
    float z = ZTk[m * Rr + lane];
    // qp[s] = sum_r z[r] * Minv[r][s]
    float qp = 0.0f;
    #pragma unroll
    for (int r = 0; r < Rr; r++)
        qp += Mi[r * 33 + lane] * __shfl_sync(0xFFFFFFFFu, z, r);
    // scores over neighbors
    for (int i0 = 0; i0 < nz; i0 += 4) {
        int c0 = cp[i0];
        int c1 = (i0 + 1 < nz) ? cp[i0 + 1] : c0;
        int c2 = (i0 + 2 < nz) ? cp[i0 + 2] : c0;
        int c3 = (i0 + 3 < nz) ? cp[i0 + 3] : c0;
        float p0 = warp_sum(qp * ZTk[c0 * Rr + lane]);
        float p1 = warp_sum(qp * ZTk[c1 * Rr + lane]);
        float p2 = warp_sum(qp * ZTk[c2 * Rr + lane]);
        float p3 = warp_sum(qp * ZTk[c3 * Rr + lane]);
        if (lane == 0) {
            ssh[w][i0] = p0;
            if (i0 + 1 < nz) ssh[w][i0 + 1] = p1;
            if (i0 + 2 < nz) ssh[w][i0 + 2] = p2;
            if (i0 + 3 < nz) ssh[w][i0 + 3] = p3;
        }
    }
    __syncwarp();
    float mx = -1e30f;
    for (int i = lane; i < nz; i += 32) mx = fmaxf(mx, ssh[w][i]);
    mx = warp_max(mx);
    float sm = 0.0f;
    for (int i = lane; i < nz; i += 32) {
        float e = expf(ssh[w][i] - mx);
        ssh[w][i] = e; sm += e;
    }
    sm = warp_sum(sm);
    float inv = 1.0f / sm;
    __syncwarp();
    // t = sum_j alpha_j * z_j
    float t = 0.0f;
    int i = 0;
    for (; i + 4 <= nz; i += 4) {
        float m0 = ZTk[cp[i]     * Rr + lane];
        float m1 = ZTk[cp[i + 1] * Rr + lane];
        float m2 = ZTk[cp[i + 2] * Rr + lane];
        float m3 = ZTk[cp[i + 3] * Rr + lane];
        t += ssh[w][i] * m0 + ssh[w][i + 1] * m1 + ssh[w][i + 2] * m2 + ssh[w][i + 3] * m3;
    }
    for (; i < nz; i++) t += ssh[w][i] * ZTk[cp[i] * Rr + lane];
    t *= inv;
    // out[r] = sum_s Minv[r][s] * t[s]
    float o = 0.0f;
    #pragma unroll
    for (int s2 = 0; s2 < Rr; s2++)
        o += Mi[lane * 33 + s2] * __shfl_sync(0xFFFFFFFFu, t, s2);
    g_Gcat[m * (Kk * Rr) + kz * Rr + lane] = o * (ETA * g_w[kz]);
}

// ---------------- agg = Gcat @ Ucat: tiled 64x64, 4x4 per thread ----------------
__global__ void k_gemm(const float* __restrict__ U) {
    __shared__ float Gs[64][33];
    __shared__ float Us[32][65];
    int n0 = blockIdx.x * 64, d0 = blockIdx.y * 64;
    int tx = threadIdx.x & 15, ty = threadIdx.x >> 4;
    float acc[4][4];
    #pragma unroll
    for (int a = 0; a < 4; a++)
        #pragma unroll
        for (int b = 0; b < 4; b++) acc[a][b] = 0.f;
    for (int k = 0; k < Kk; k++) {
        __syncthreads();
        #pragma unroll
        for (int q = 0; q < 8; q++) {
            int idx = threadIdx.x + 256 * q;
            int gi = idx >> 5, gr = idx & 31;
            Gs[gi][gr] = g_Gcat[(n0 + gi) * (Kk * Rr) + k * Rr + gr];
            Us[gr][gi] = U[k * Dd * Rr + (d0 + gi) * Rr + gr];
        }
        __syncthreads();
        #pragma unroll
        for (int r = 0; r < Rr; r++) {
            float a[4], b[4];
            #pragma unroll
            for (int q = 0; q < 4; q++) a[q] = Gs[ty * 4 + q][r];
            #pragma unroll
            for (int p = 0; p < 4; p++) b[p] = Us[r][tx * 4 + p];
            #pragma unroll
            for (int q = 0; q < 4; q++)
                #pragma unroll
                for (int p = 0; p < 4; p++) acc[q][p] += a[q] * b[p];
        }
    }
    #pragma unroll
    for (int q = 0; q < 4; q++) {
        float4 v = make_float4(acc[q][0], acc[q][1], acc[q][2], acc[q][3]);
        *(float4*)&g_agg[(size_t)(n0 + ty * 4 + q) * Dd + d0 + tx * 4] = v;
    }
}

// ---------------- finalize: inline H3 gather + threshold + residual + LN; 4 rows/block ----------------
__global__ void k_finalize(const float* __restrict__ H0, const float* __restrict__ thr,
                           const float* __restrict__ gam, const float* __restrict__ bet,
                           float* __restrict__ out) {
    int rl = threadIdx.x >> 6, t64 = threadIdx.x & 63;
    int m = blockIdx.x * 4 + rl;
    __shared__ int   csh[4][MAXNZ];
    __shared__ float vsh[4][MAXNZ];
    __shared__ float wred[8][2];
    int nzp = g_nnzp[m];
    for (int i = t64; i < nzp; i += 64) {
        csh[rl][i] = g_cols[m * MAXNZ + i];
        vsh[rl][i] = g_vals[m * MAXNZ + i];
    }
    __syncthreads();
    const float4* H0_4 = (const float4*)H0;
    const float4* H1_4 = (const float4*)g_H1;
    const float4* H2_4 = (const float4*)g_H2;
    const float4* ag4  = (const float4*)g_agg;
    int idx4 = m * 64 + t64;
    float4 x  = H0_4[idx4];
    float4 h1 = H1_4[idx4];
    float4 h2 = H2_4[idx4];
    float4 ag = ag4[idx4];
    float4 h3 = make_float4(0.f, 0.f, 0.f, 0.f);
    for (int i = 0; i < nzp; i += 4) {
        float4 x0 = H2_4[csh[rl][i]     * 64 + t64];
        float4 x1 = H2_4[csh[rl][i + 1] * 64 + t64];
        float4 x2 = H2_4[csh[rl][i + 2] * 64 + t64];
        float4 x3 = H2_4[csh[rl][i + 3] * 64 + t64];
        float v0 = vsh[rl][i], v1 = vsh[rl][i + 1], v2 = vsh[rl][i + 2], v3 = vsh[rl][i + 3];
        h3.x += v0*x0.x + v1*x1.x + v2*x2.x + v3*x3.x;
        h3.y += v0*x0.y + v1*x1.y + v2*x2.y + v3*x3.y;
        h3.z += v0*x0.z + v1*x1.z + v2*x2.z + v3*x3.z;
        h3.w += v0*x0.w + v1*x1.w + v2*x2.w + v3*x3.w;
    }
    float l0 = g_lap[0], l1 = g_lap[1], l2 = g_lap[2];
    float4 t4 = ((const float4*)thr)[t64];
    float y[4];
    {
        float xs[4] = {x.x, x.y, x.z, x.w};
        float a1[4] = {h1.x, h1.y, h1.z, h1.w};
        float a2[4] = {h2.x, h2.y, h2.z, h2.w};
        float a3[4] = {h3.x, h3.y, h3.z, h3.w};
        float ags[4] = {ag.x, ag.y, ag.z, ag.w};
        float ts[4] = {t4.x, t4.y, t4.z, t4.w};
        #pragma unroll
        for (int q = 0; q < 4; q++) {
            float lap = l0 * (xs[q] - a1[q]) + l1 * (a1[q] - a2[q]) + l2 * (a2[q] - a3[q]);
            float h = xs[q] + ags[q] - ETA * lap;
            float a = fabsf(h) - ts[q];
            float yv = (a > 0.0f) ? copysignf(a, h) : 0.0f;
            y[q] = yv + xs[q];
        }
    }
    float s1 = y[0] + y[1] + y[2] + y[3];
    float s2 = y[0]*y[0] + y[1]*y[1] + y[2]*y[2] + y[3]*y[3];
    s1 = warp_sum(s1); s2 = warp_sum(s2);
    int w = threadIdx.x >> 5, lane = threadIdx.x & 31;
    if (lane == 0) { wred[w][0] = s1; wred[w][1] = s2; }
    __syncthreads();
    float mu  = (wred[rl*2][0] + wred[rl*2+1][0]) * (1.0f / Dd);
    float ex2 = (wred[rl*2][1] + wred[rl*2+1][1]) * (1.0f / Dd);
    float inv_sd = rsqrtf(ex2 - mu * mu + LN_EPS);
    float4 g4 = ((const float4*)gam)[t64];
    float4 b4 = ((const float4*)bet)[t64];
    float4 o4;
    o4.x = (y[0] - mu) * inv_sd * g4.x + b4.x;
    o4.y = (y[1] - mu) * inv_sd * g4.y + b4.y;
    o4.z = (y[2] - mu) * inv_sd * g4.z + b4.z;
    o4.w = (y[3] - mu) * inv_sd * g4.w + b4.w;
    ((float4*)out)[idx4] = o4;
}

// ---------------- lap_smooth = sum(H_out * (H_out - A@H_out)); 4 rows/block ----------------
__global__ void k_lapsm(const float* __restrict__ out, float* __restrict__ dst) {
    int rl = threadIdx.x >> 6, t64 = threadIdx.x & 63;
    int m = blockIdx.x * 4 + rl;
    __shared__ int   csh[4][MAXNZ];
    __shared__ float vsh[4][MAXNZ];
    __shared__ float wred[8];
    int nzp = g_nnzp[m];
    for (int i = t64; i < nzp; i += 64) {
        csh[rl][i] = g_cols[m * MAXNZ + i];
        vsh[rl][i] = g_vals[m * MAXNZ + i];
    }
    __syncthreads();
    const float4* o4 = (const float4*)out;
    float4 o = o4[m * 64 + t64];
    float4 ah = make_float4(0.f, 0.f, 0.f, 0.f);
    for (int i = 0; i < nzp; i += 4) {
        float4 x0 = o4[csh[rl][i]     * 64 + t64];
        float4 x1 = o4[csh[rl][i + 1] * 64 + t64];
        float4 x2 = o4[csh[rl][i + 2] * 64 + t64];
        float4 x3 = o4[csh[rl][i + 3] * 64 + t64];
        float v0 = vsh[rl][i], v1 = vsh[rl][i + 1], v2 = vsh[rl][i + 2], v3 = vsh[rl][i + 3];
        ah.x += v0*x0.x + v1*x1.x + v2*x2.x + v3*x3.x;
        ah.y += v0*x0.y + v1*x1.y + v2*x2.y + v3*x3.y;
        ah.z += v0*x0.z + v1*x1.z + v2*x2.z + v3*x3.z;
        ah.w += v0*x0.w + v1*x1.w + v2*x2.w + v3*x3.w;
    }
    float part = o.x * (o.x - ah.x) + o.y * (o.y - ah.y) + o.z * (o.z - ah.z) + o.w * (o.w - ah.w);
    int w = threadIdx.x >> 5, lane = threadIdx.x & 31;
    float s = warp_sum(part);
    if (lane == 0) wred[w] = s;
    __syncthreads();
    if (threadIdx.x == 0) {
        float t = 0.0f;
        #pragma unroll
        for (int q = 0; q < 8; q++) t += wred[q];
        atomicAdd(dst, t);
    }
}

// ---------------- launch ----------------
extern "C" void kernel_launch(void* const* d_in, const int* in_sizes, int n_in,
                              void* d_out, int out_size) {
    const float* H   = (const float*)d_in[0];
    const float* A   = (const float*)d_in[1];
    const float* U   = (const float*)d_in[4];
    const float* lam = (const float*)d_in[5];
    const float* hw  = (const float*)d_in[6];
    const float* thr = (const float*)d_in[7];
    const float* gam = (const float*)d_in[8];
    const float* bet = (const float*)d_in[9];
    float* out  = (float*)d_out;
    float* tail = out + (size_t)Nn * Dd;   // [orth, lap_smooth, w0, w1, w2]

    cudaMemsetAsync(tail, 0, 2 * sizeof(float));   // zero orth + lap_smooth accumulators

    k_csr<<<Nn / 8, 256>>>(A);

    k_spmm<<<Nn / 4, 256>>>(H, 0, 1);   // H1 = A @ H
    k_spmm<<<Nn / 4, 256>>>(H, 1, 2);   // H2 = A @ H1

    k_ZM<<<dim3(32, Kk), 256>>>(H, U);  // ZT + partial M, vectorized
    k_mid<<<10, 1024>>>(U, lam, hw, tail);  // cholinv(3) + orth(6) + setup(1)
    k_attn<<<dim3(Nn / 8, Kk), 256>>>();

    k_gemm<<<dim3(Nn / 64, Dd / 64), 256>>>(U);
    k_finalize<<<Nn / 4, 256>>>(H, thr, gam, bet, out);  // includes H3 gather
    k_lapsm<<<Nn / 4, 256>>>(out, tail + 1);
}